// round 15
// baseline (speedup 1.0000x reference)
#include <cuda_runtime.h>
#include <cstdint>

#define B_      2
#define I_      1024
#define J_      1024
#define C_      64
#define TJ      64          // j-tile (2 warp-iters of 32 j)
#define NT      (J_/TJ)     // 16
#define ROWS    4           // rows per block = warps per block
#define THREADS 128
#define KPAD    17          // float4 per K row in smem (conflict-free)

// sigmoid(x)-0.5 = sgn(x)*(P(e)-0.5), e = 2^(-|x'|), x' = -log2e*x
// P quartic minimax of 1/(1+e) on [0,1]; measured output rel_err ~1e-4
#define PC4  0.156867f
#define PC3 -0.542300f
#define PC2  0.871982f
#define PC1 -0.986114f
#define PC0  0.499747f     /* c0 - 0.5 folded (>= 0 on [0,1]) */
#define NLOG2E -1.44269504f
#define NLN2   -0.69314718f

__device__ __forceinline__ float ex2a(float x) {
    float y; asm("ex2.approx.f32 %0, %1;" : "=f"(y) : "f"(x)); return y;
}
__device__ __forceinline__ float sig_c(float xp) {   // xp = -log2e*x ; returns sigmoid(x)-0.5
    // -|xp| via one LOP (deterministic; no reliance on modifier folding)
    const float nax = __uint_as_float(__float_as_uint(xp) | 0x80000000u);
    const float e = ex2a(nax);
    float r = fmaf(PC4, e, PC3);
    r = fmaf(r, e, PC2);
    r = fmaf(r, e, PC1);
    r = fmaf(r, e, PC0);                             // P(e)-0.5 in [0, 0.5]
    // flip sign iff xp >= +0  (original x <= 0): single LOP3  r ^ (~xp & signbit)
    return __uint_as_float(__float_as_uint(r) ^ ((~__float_as_uint(xp)) & 0x80000000u));
}
__device__ __forceinline__ void cp16(uint32_t s, const void* g) {
    asm volatile("cp.async.cg.shared.global [%0], [%1], 16;" :: "r"(s), "l"(g));
}
__device__ __forceinline__ void cp_commit() { asm volatile("cp.async.commit_group;"); }
template<int N> __device__ __forceinline__ void cp_wait() {
    asm volatile("cp.async.wait_group %0;" :: "n"(N));
}

__global__ __launch_bounds__(THREADS, 3)
void fused_attn_mlp_kernel(const float* __restrict__ Q,
                           const float* __restrict__ K,
                           const float* __restrict__ bias,
                           const float* __restrict__ mask,
                           float* __restrict__ out,      // [B,I,C]
                           float* __restrict__ attn)     // [B,I,J]
{
    __shared__ __align__(16) float4 kbuf[2][TJ * KPAD];  // 2 x ~17.4KB
    __shared__ __align__(16) float4 sq[ROWS][16];        // q' = -log2e * Q row
    __shared__ __align__(16) float4 sb[16];              // b' = -log2e * bias

    const int tid  = threadIdx.x;
    const int lane = tid & 31;
    const int w    = tid >> 5;          // warp = local row
    const int row  = blockIdx.x * ROWS + w;
    const int b    = (blockIdx.x * ROWS) >> 10;

    // stage b' and q' (pre-scaled by -log2e)
    if (tid < C_) ((float*)sb)[tid] = NLOG2E * bias[tid];
    #pragma unroll
    for (int idx = tid; idx < ROWS * C_; idx += THREADS) {
        int r = idx >> 6, c = idx & 63;
        ((float*)sq)[idx] = NLOG2E * Q[(size_t)(blockIdx.x * ROWS + r) * C_ + c];
    }

    const uint32_t sbase0 = (uint32_t)__cvta_generic_to_shared(&kbuf[0][0]);
    const uint32_t sbase1 = (uint32_t)__cvta_generic_to_shared(&kbuf[1][0]);
    const float4* Kb = (const float4*)K + (size_t)b * J_ * 16;

    // prefetch tile 0 (64 rows x 16 chunks = 1024 float4, 8 per thread)
    {
        #pragma unroll
        for (int r = 0; r < (TJ*16)/THREADS; ++r) {
            int idx = tid + r * THREADS;
            int rr = idx >> 4, cc = idx & 15;
            cp16(sbase0 + (uint32_t)(rr * KPAD + cc) * 16, Kb + (size_t)rr * 16 + cc);
        }
        cp_commit();
    }
    __syncthreads();

    // nbsum = -sum(bias) = -NLN2 * sum(b')
    float nbsum;
    {
        float s = 0.f;
        #pragma unroll
        for (int c = 0; c < C_; ++c) s += ((const float*)sb)[c];
        nbsum = -NLN2 * s;
    }

    float4 acc[16];
    #pragma unroll
    for (int c = 0; c < 16; ++c) acc[c] = make_float4(0.f, 0.f, 0.f, 0.f);
    float msum = 0.f;

    const float* mrow = mask + (size_t)row * J_;
    float*       arow = attn + (size_t)row * J_;

    for (int t = 0; t < NT; ++t) {
        // masks for this tile (independent of smem state)
        float mj[TJ / 32];
        #pragma unroll
        for (int u = 0; u < TJ / 32; ++u)
            mj[u] = mrow[t * TJ + u * 32 + lane];

        if (t + 1 < NT) {
            const float4* src = Kb + (size_t)(t + 1) * TJ * 16;
            uint32_t dst = ((t + 1) & 1) ? sbase1 : sbase0;
            #pragma unroll
            for (int r = 0; r < (TJ*16)/THREADS; ++r) {
                int idx = tid + r * THREADS;
                int rr = idx >> 4, cc = idx & 15;
                cp16(dst + (uint32_t)(rr * KPAD + cc) * 16, src + (size_t)rr * 16 + cc);
            }
            cp_commit();
            cp_wait<1>();
        } else {
            cp_wait<0>();
        }
        __syncthreads();

        const float4* kb = kbuf[t & 1];

        #pragma unroll
        for (int u = 0; u < TJ / 32; ++u) {
            const int jj = u * 32 + lane;        // this lane's j in the tile
            const float4* kr = kb + jj * KPAD;
            const float m = mj[u];

            float hs0 = 0.f, hs1 = 0.f, hs2 = 0.f, hs3 = 0.f;
            #pragma unroll
            for (int c = 0; c < 16; ++c) {
                const float4 k4 = kr[c];
                const float4 q4 = sq[w][c];      // hoisted to regs by ptxas
                const float4 b4 = sb[c];
                const float x0 = fmaf(q4.x, k4.x, b4.x);   // x' = -log2e*(qk+b)
                const float x1 = fmaf(q4.y, k4.y, b4.y);
                const float x2 = fmaf(q4.z, k4.z, b4.z);
                const float x3 = fmaf(q4.w, k4.w, b4.w);
                hs0 += x0; hs1 += x1; hs2 += x2; hs3 += x3;
                acc[c].x = fmaf(sig_c(x0), m, acc[c].x);
                acc[c].y = fmaf(sig_c(x1), m, acc[c].y);
                acc[c].z = fmaf(sig_c(x2), m, acc[c].z);
                acc[c].w = fmaf(sig_c(x3), m, acc[c].w);
            }
            const float hs = (hs0 + hs1) + (hs2 + hs3);    // full 64-ch sum of x'
            // dot(q,k) = NLN2 * sum(x') - sum(bias)
            arow[t * TJ + jj] = fmaf(hs, NLN2, nbsum) * m;
            msum += m;
        }
        __syncthreads();   // all warps done reading tile t before it is overwritten
    }

    // one-time warp butterfly reduction of acc[64] + msum
    #pragma unroll
    for (int s = 1; s < 32; s <<= 1) {
        msum += __shfl_xor_sync(0xffffffffu, msum, s);
        #pragma unroll
        for (int c = 0; c < 16; ++c) {
            acc[c].x += __shfl_xor_sync(0xffffffffu, acc[c].x, s);
            acc[c].y += __shfl_xor_sync(0xffffffffu, acc[c].y, s);
            acc[c].z += __shfl_xor_sync(0xffffffffu, acc[c].z, s);
            acc[c].w += __shfl_xor_sync(0xffffffffu, acc[c].w, s);
        }
    }
    if (lane == 0) {
        const float half_m = 0.5f * msum;
        const float inv = __fdividef(1.0f, msum);
        float* orow = out + (size_t)row * C_;
        #pragma unroll
        for (int c = 0; c < 16; ++c) {
            float4 o;
            o.x = (acc[c].x + half_m) * inv;
            o.y = (acc[c].y + half_m) * inv;
            o.z = (acc[c].z + half_m) * inv;
            o.w = (acc[c].w + half_m) * inv;
            *(float4*)(orow + c * 4) = o;
        }
    }
}

extern "C" void kernel_launch(void* const* d_in, const int* in_sizes, int n_in,
                              void* d_out, int out_size) {
    const float* Q    = (const float*)d_in[0];
    const float* K    = (const float*)d_in[1];
    const float* bias = (const float*)d_in[2];
    const float* mask = (const float*)d_in[3];
    float* out  = (float*)d_out;                       // [B,I,C] first
    float* attn = (float*)d_out + (size_t)B_*I_*C_;    // [B,I,J] second

    dim3 grid(B_ * I_ / ROWS);
    dim3 block(THREADS);
    fused_attn_mlp_kernel<<<grid, block>>>(Q, K, bias, mask, out, attn);
}